// round 7
// baseline (speedup 1.0000x reference)
#include <cuda_runtime.h>
#include <cstddef>
#include <cstdint>

// HardDTW max-plus scan — in-register halo wavefront.
//
//   out[b,0,k] = x[b,0,k]
//   out[b,t,k] = x[b,t,k] + max(out[b,t-1,k], out[b,t-1,k-1])   (k-1 < 0 -> -inf)
//
// 2 CTAs per batch (grid=B*2), 256 threads (8 warps). Thread owns 2 columns
// (v23) and carries a 2-column halo (v01) = left neighbor's columns, letting
// it run 2 steps with no cross-thread traffic. Every 2 steps ("group"), a
// batched refresh: 2x shfl_up pulls the neighbor's fresh owned pair; lane 0
// takes the upstream warp's boundary slot. Warp levels skewed 1 chunk
// (16 steps) apart, 1 __syncthreads per epoch. Cross-CTA seam via gmem
// mailbox + release/acquire flag (2-epoch margin, poll normally satisfied).

namespace {
constexpr int T = 2048;
constexpr int K = 1024;
constexpr int MAXB = 32;
constexpr int THREADS = 256;
constexpr int NWARP = 8;
constexpr int CHUNK = 16;
constexpr int NCHUNK = T / CHUNK;                   // 128
constexpr int CROSS = 9;                            // CTA1 warp0 level
constexpr int NEPOCH = NCHUNK + CROSS + NWARP - 1;  // 144
constexpr int RS2 = K / 2;                          // float2 per full row
constexpr int NSLOT = 8;                            // boundary slots per chunk
constexpr int DQ = 32;                              // owned-x prefetch depth
constexpr int DH = 16;                              // halo-x prefetch depth
}

__device__ float2 eg_edges[MAXB][NCHUNK][NSLOT];   // cross-CTA boundary slots
__device__ int    eg_flag[MAXB][32];               // [b][0]

__global__ void harddtw_init_kernel() {
    if (threadIdx.x < MAXB) eg_flag[threadIdx.x][0] = 0;
}

__global__ __launch_bounds__(THREADS, 1)
void harddtw_halo_kernel(const float* __restrict__ x, float* __restrict__ out) {
    __shared__ __align__(16) float2 edges[2][NWARP][NSLOT];

    const int tid  = threadIdx.x;
    const int lane = tid & 31;
    const int warp = tid >> 5;
    const int half = blockIdx.x & 1;
    const int b    = blockIdx.x >> 1;
    const int level = half ? (CROSS + warp) : warp;
    const float NI = __int_as_float(0xff800000);

    // Owned float2 index within a row; halo float2 = index-1 (clamped at 0).
    const int colf2 = half * (RS2 / 2) + warp * 32 + lane;
    const float2* __restrict__ xrow =
        reinterpret_cast<const float2*>(x + (size_t)b * T * K);
    float2* __restrict__ orow =
        reinterpret_cast<float2*>(out + (size_t)b * T * K);
    const float2* __restrict__ xo_p = xrow + colf2;
    const float2* __restrict__ xh_p = xrow + ((colf2 == 0) ? 0 : (colf2 - 1));
    float2* __restrict__ o_p = orow + colf2;

    const bool sprod = (warp < NWARP - 1) && (lane == 31);
    const bool gprod = (half == 0) && (warp == NWARP - 1) && (lane == 31);
    const bool gcons = (half == 1) && (warp == 0);
    const bool lvl0  = (level == 0);
    const int  pw    = (warp == 0) ? 0 : (warp - 1);
    int* const flagp = &eg_flag[b][0];

    // ── Prefetch queues (parity rings: chunk c uses half (c&1)) ──
    float2 xq[DQ];
#pragma unroll
    for (int j = 0; j < DQ; ++j) xq[j] = xo_p[(size_t)j * RS2];

    float2 xhq[DH];
    // chunk-0 pattern: slot0=row0 (seed), slot s=row 2s-1 (groups)
    xhq[0] = xh_p[0];
#pragma unroll
    for (int s = 1; s < 8; ++s) xhq[s] = xh_p[(size_t)(2 * s - 1) * RS2];
    // chunk-1 pattern: slot 8+s = row 16+2s
#pragma unroll
    for (int s = 0; s < 8; ++s) xhq[8 + s] = xh_p[(size_t)(16 + 2 * s) * RS2];

    float2 v01, v23;          // halo pair / owned pair
    v01.x = NI; v01.y = NI; v23.x = NI; v23.y = NI;

    for (int e = 0; e < NEPOCH; ++e) {
        const int c = e - level;
        if (0 <= c && c < NCHUNK) {
            const int t0 = c * CHUNK;
            const int qb = (c & 1) * 16;
            const int hb = (c & 1) * 8;

            // ── Boundary slots from upstream level ──
            float4 q[4];
            if (lvl0) {
#pragma unroll
                for (int i = 0; i < 4; ++i) q[i] = make_float4(NI, NI, NI, NI);
            } else if (gcons) {
                int f;
                do {
                    asm volatile("ld.acquire.gpu.global.s32 %0, [%1];"
                                 : "=r"(f) : "l"(flagp) : "memory");
                } while (f < c + 1);
                const float4* src =
                    reinterpret_cast<const float4*>(&eg_edges[b][c][0]);
#pragma unroll
                for (int i = 0; i < 4; ++i) q[i] = __ldcg(src + i);
            } else {
                const float4* src =
                    reinterpret_cast<const float4*>(&edges[(e - 1) & 1][pw][0]);
#pragma unroll
                for (int i = 0; i < 4; ++i) q[i] = src[i];
            }

            auto bslot = [&](int g) -> float2 {
                const float4 v = q[g >> 1];
                return (g & 1) ? make_float2(v.z, v.w) : make_float2(v.x, v.y);
            };
            auto publish = [&](int s) {
                if (sprod) edges[e & 1][warp][s] = v23;
                if (gprod) eg_edges[b][c][s] = v23;
            };
            auto refresh = [&](float2 bs) {
                float h0 = __shfl_up_sync(0xffffffffu, v23.x, 1);
                float h1 = __shfl_up_sync(0xffffffffu, v23.y, 1);
                if (lane == 0) { h0 = bs.x; h1 = bs.y; }
                v01.x = h0; v01.y = h1;
            };
            auto stepA = [&](float2 xo, float xhh) {   // also advances halo col
                float n3 = xo.y + fmaxf(v23.y, v23.x);
                float n2 = xo.x + fmaxf(v23.x, v01.y);
                float n1 = xhh  + fmaxf(v01.y, v01.x);
                v23.x = n2; v23.y = n3; v01.y = n1;
            };
            auto stepB = [&](float2 xo) {              // halo col goes stale
                float n3 = xo.y + fmaxf(v23.y, v23.x);
                float n2 = xo.x + fmaxf(v23.x, v01.y);
                v23.x = n2; v23.y = n3;
            };
            auto store = [&](int t) { o_p[(size_t)t * RS2] = v23; };
            auto refillq = [&](int j) {
                if (t0 + j + DQ < T) xq[qb + j] = xo_p[(size_t)(t0 + j + DQ) * RS2];
            };
            auto refillh = [&](int s) {
                if (t0 + 32 + 2 * s < T)
                    xhq[hb + s] = xh_p[(size_t)(t0 + 32 + 2 * s) * RS2];
            };

            if (c == 0) {
                // j=0 seed: out[0] = x[0] (halo seeded from x too)
                v23 = xq[qb + 0];
                v01 = xhq[hb + 0];
                if (lvl0 && lane == 0) { v01.x = NI; v01.y = NI; }
                store(0); refillq(0); refillh(0);
                // Group 0: j=1,2 (no refresh; v01 valid from seed)
                stepA(xq[qb + 1], xhq[hb + 1].y); store(1); refillq(1); refillh(1);
                stepB(xq[qb + 2]);                store(2); refillq(2);
                publish(0);
#pragma unroll
                for (int k = 1; k < 7; ++k) {
                    refresh(bslot(k - 1));
                    stepA(xq[qb + 2 * k + 1], xhq[hb + k + 1].y);
                    store(2 * k + 1); refillq(2 * k + 1); refillh(k + 1);
                    stepB(xq[qb + 2 * k + 2]);
                    store(2 * k + 2); refillq(2 * k + 2);
                    publish(k);
                }
                // j=15 (single)
                refresh(bslot(6));
                stepB(xq[qb + 15]); store(15); refillq(15);
            } else {
                publish(7);   // pre-chunk carry out[t0-1] (top owned pair)
#pragma unroll
                for (int g = 0; g < 8; ++g) {
                    refresh(bslot(g == 0 ? 7 : g - 1));
                    stepA(xq[qb + 2 * g], xhq[hb + g].y);
                    store(t0 + 2 * g); refillq(2 * g); refillh(g);
                    stepB(xq[qb + 2 * g + 1]);
                    store(t0 + 2 * g + 1); refillq(2 * g + 1);
                    if (g < 7) publish(g);
                }
            }

            if (gprod) {
                int v = c + 1;
                asm volatile("st.release.gpu.global.s32 [%0], %1;"
                             :: "l"(flagp), "r"(v) : "memory");
            }
        }
        __syncthreads();
    }
}

extern "C" void kernel_launch(void* const* d_in, const int* in_sizes, int n_in,
                              void* d_out, int out_size) {
    const float* x = (const float*)d_in[0];
    float* out = (float*)d_out;
    const int B = in_sizes[0] / (T * K);
    harddtw_init_kernel<<<1, 32>>>();
    harddtw_halo_kernel<<<B * 2, THREADS>>>(x, out);
}

// round 8
// speedup vs baseline: 2.3797x; 2.3797x over previous
#include <cuda_runtime.h>
#include <cstddef>

// HardDTW max-plus scan — lean monolithic wavefront (R3 skeleton + instruction diet).
//
//   out[b,0,k] = x[b,0,k]
//   out[b,t,k] = x[b,t,k] + max(out[b,t-1,k], out[b,t-1,k-1])   (k-1 < 0 -> -inf)
//
// One CTA per batch (B=32), 256 threads (8 warps), thread owns 4 consecutive k
// (float4 carry). Warp w processes chunk c = e - w (16 steps) at epoch e; one
// __syncthreads per epoch. Upstream edges via double-buffered smem, bulk-read
// into registers (bvq) at chunk start and bulk-published (ew -> 4x STS.128) at
// chunk end. Inner step is branch-free: LDG + STG + 1 shfl + 1 sel + 8 FP ops,
// all register arrays compile-time indexed, addresses are immediate offsets.

namespace {
constexpr int T = 2048;
constexpr int K = 1024;
constexpr int THREADS = 256;
constexpr int NWARP = 8;
constexpr int CHUNK = 16;
constexpr int NCHUNK = T / CHUNK;            // 128
constexpr int NEPOCH = NCHUNK + NWARP - 1;   // 135
constexpr int RS = K / 4;                    // float4 per row = 256
}

__device__ __forceinline__ float bsel(const float4* q, int j) {
    const float4 v = q[j >> 2];
    switch (j & 3) {
        case 0: return v.x;
        case 1: return v.y;
        case 2: return v.z;
        default: return v.w;
    }
}

// One DP step. j must be a compile-time constant (full unroll). RF = refill.
#define DTW_STEP(j, RF)                                          \
    do {                                                         \
        const float4 xv = xq[(j)];                               \
        if (RF) xq[(j)] = xn[(j) * RS];                          \
        float up = __shfl_up_sync(0xffffffffu, cur.w, 1);        \
        if (lane == 0) up = bsel(bvq, (j));                      \
        float4 n;                                                \
        n.x = xv.x + fmaxf(cur.x, up);                           \
        n.y = xv.y + fmaxf(cur.y, cur.x);                        \
        n.z = xv.z + fmaxf(cur.z, cur.y);                        \
        n.w = xv.w + fmaxf(cur.w, cur.z);                        \
        cur = n;                                                 \
        op[(j) * RS] = cur;                                      \
        if ((j) + 1 < CHUNK) ew[(j) + 1] = cur.w;                \
    } while (0)

__global__ __launch_bounds__(THREADS, 1)
void harddtw_lean_kernel(const float* __restrict__ x, float* __restrict__ out) {
    __shared__ __align__(16) float edges[2][NWARP][CHUNK];

    const int tid  = threadIdx.x;
    const int lane = tid & 31;
    const int warp = tid >> 5;
    const int b    = blockIdx.x;
    const float NI = __int_as_float(0xff800000);

    const float4* __restrict__ xr =
        reinterpret_cast<const float4*>(x + (size_t)b * T * K) + tid;
    float4* __restrict__ orow =
        reinterpret_cast<float4*>(out + (size_t)b * T * K) + tid;

    const bool sprod = (warp < NWARP - 1) && (lane == 31);
    const int pw = (warp == 0) ? 0 : (warp - 1);

    // Prefetch chunk 0 (rows 0..15). Compile-time indices only.
    float4 xq[CHUNK];
#pragma unroll
    for (int j = 0; j < CHUNK; ++j) xq[j] = xr[(size_t)j * RS];

    float4 cur = make_float4(NI, NI, NI, NI);

    for (int e = 0; e < NEPOCH; ++e) {
        const int c = e - warp;
        if (0 <= c && c < NCHUNK) {
            const int t0 = c * CHUNK;
            const int eb = e & 1;

            // Boundary vector: upstream warp's edges (epoch e-1), or -inf for warp 0.
            float4 bvq[4];
            if (warp == 0) {
#pragma unroll
                for (int i = 0; i < 4; ++i) bvq[i] = make_float4(NI, NI, NI, NI);
            } else {
                const float4* src =
                    reinterpret_cast<const float4*>(edges[(e - 1) & 1][pw]);
#pragma unroll
                for (int i = 0; i < 4; ++i) bvq[i] = src[i];
            }

            // Edge values to publish: ew[s] = out[t0+s-1].w (ew[0] = carry-in).
            float ew[CHUNK];
            ew[0] = cur.w;

            // Per-chunk base pointers; inner offsets are immediates.
            float4* op = orow + (size_t)t0 * RS;
            const float4* xn = xr + (size_t)(t0 + CHUNK) * RS;

            if (c == 0) {
                // Init row: out[0] = x[0].
                cur = xq[0];
                xq[0] = xn[0];
                op[0] = cur;
                ew[1] = cur.w;
#pragma unroll
                for (int j = 1; j < CHUNK; ++j) DTW_STEP(j, true);
            } else if (c + 1 < NCHUNK) {
#pragma unroll
                for (int j = 0; j < CHUNK; ++j) DTW_STEP(j, true);
            } else {
#pragma unroll
                for (int j = 0; j < CHUNK; ++j) DTW_STEP(j, false);
            }

            // Batched edge publish (lane 31 of warps 0..6): 4x STS.128.
            if (sprod) {
                float4* dst = reinterpret_cast<float4*>(edges[eb][warp]);
                dst[0] = make_float4(ew[0],  ew[1],  ew[2],  ew[3]);
                dst[1] = make_float4(ew[4],  ew[5],  ew[6],  ew[7]);
                dst[2] = make_float4(ew[8],  ew[9],  ew[10], ew[11]);
                dst[3] = make_float4(ew[12], ew[13], ew[14], ew[15]);
            }
        }
        __syncthreads();
    }
}

extern "C" void kernel_launch(void* const* d_in, const int* in_sizes, int n_in,
                              void* d_out, int out_size) {
    const float* x = (const float*)d_in[0];
    float* out = (float*)d_out;
    const int B = in_sizes[0] / (T * K);
    harddtw_lean_kernel<<<B, THREADS>>>(x, out);
}

// round 9
// speedup vs baseline: 2.9035x; 1.2201x over previous
#include <cuda_runtime.h>
#include <cstddef>

// HardDTW max-plus scan — R3 wavefront skeleton with deeper (16) prefetch.
//
//   out[b,0,k] = x[b,0,k]
//   out[b,t,k] = x[b,t,k] + max(out[b,t-1,k], out[b,t-1,k-1])   (k-1 < 0 -> -inf)
//
// One CTA per batch (B=32), 256 threads (8 warps), thread owns 4 consecutive k
// (float4 carry in registers). Warp w processes chunk c = e - w (16 steps) at
// epoch e; one __syncthreads per epoch. Upstream edges (lane-31 cur.w of warp
// w-1) pass through a double-buffered smem array indexed by epoch parity.
// x prefetched with a rolling 16-deep float4 register queue: the load issued
// at step j of chunk c is consumed at step j of chunk c+1, putting 16 loads
// (8 KB/warp, 64 KB/SM) in flight to cover DRAM latency (Little's law).

namespace {
constexpr int T = 2048;
constexpr int K = 1024;
constexpr int THREADS = 256;
constexpr int NWARP = THREADS / 32;          // 8
constexpr int RS = K / 4;                    // float4 per row
constexpr int CHUNK = 16;
constexpr int D = 16;                        // prefetch depth == CHUNK
constexpr int NCHUNK = T / CHUNK;            // 128
constexpr int NEPOCH = NCHUNK + NWARP - 1;   // 135
}

__global__ __launch_bounds__(THREADS, 1)
void harddtw_wave16_kernel(const float* __restrict__ x, float* __restrict__ out) {
    // edges[p][w][j] : upstream boundary needed by warp w+1 at step t0+j of a
    // chunk, i.e. warp w's edge value at step t0+j-1 (slot 0 = last edge of
    // warp w's previous chunk).
    __shared__ float edges[2][NWARP][CHUNK];

    const int tid  = threadIdx.x;
    const int lane = tid & 31;
    const int warp = tid >> 5;
    const int b    = blockIdx.x;
    const float NEG_INF = __int_as_float(0xff800000);

    const float4* __restrict__ xr =
        reinterpret_cast<const float4*>(x + (size_t)b * T * K) + tid;
    float4* __restrict__ orow =
        reinterpret_cast<float4*>(out + (size_t)b * T * K) + tid;

    const bool prod = (warp < NWARP - 1) && (lane == 31);
    const int pw = (warp == 0) ? 0 : (warp - 1);   // safe upstream index
    const int bl = (lane < CHUNK) ? lane : (CHUNK - 1);

    // Preload chunk 0 (rows 0..15) into the rolling queue.
    float4 xq[D];
#pragma unroll
    for (int j = 0; j < D; ++j) xq[j] = xr[(size_t)j * RS];

    float4 cur = make_float4(NEG_INF, NEG_INF, NEG_INF, NEG_INF);

    for (int e = 0; e < NEPOCH; ++e) {
        const int c = e - warp;
        if (0 <= c && c < NCHUNK) {
            const int t0 = c * CHUNK;

            // Boundary vector from upstream warp (written during epoch e-1).
            float bv = edges[(e - 1) & 1][pw][bl];

            // Publish slot 0 for downstream: our edge at step t0-1
            // (end-of-previous-chunk carry; unused garbage when c == 0).
            if (prod) edges[e & 1][warp][0] = cur.w;

#pragma unroll
            for (int j = 0; j < CHUNK; ++j) {
                const int t = t0 + j;
                const float4 xv = xq[j];
                if (c + 1 < NCHUNK) xq[j] = xr[(size_t)(t + D) * RS];

                if (c == 0 && j == 0) {
                    cur = xv;  // init row: out[0] = x[0]
                } else {
                    float up = __shfl_up_sync(0xffffffffu, cur.w, 1);
                    const float bc = __shfl_sync(0xffffffffu, bv, j);
                    if (lane == 0) up = (warp == 0) ? NEG_INF : bc;

                    float4 n;
                    n.x = xv.x + fmaxf(cur.x, up);
                    n.y = xv.y + fmaxf(cur.y, cur.x);
                    n.z = xv.z + fmaxf(cur.z, cur.y);
                    n.w = xv.w + fmaxf(cur.w, cur.z);
                    cur = n;
                }

                orow[(size_t)t * RS] = cur;
                if (j < CHUNK - 1) {
                    if (prod) edges[e & 1][warp][j + 1] = cur.w;
                }
            }
        }
        __syncthreads();
    }
}

extern "C" void kernel_launch(void* const* d_in, const int* in_sizes, int n_in,
                              void* d_out, int out_size) {
    const float* x = (const float*)d_in[0];
    float* out = (float*)d_out;
    const int B = in_sizes[0] / (T * K);
    harddtw_wave16_kernel<<<B, THREADS>>>(x, out);
}